// round 6
// baseline (speedup 1.0000x reference)
#include <cuda_runtime.h>

// LSTM T=4096, B=2048, I=2, H=4, L=4. Gate order i,f,g,o.
// 8 lanes per batch element, 4 batches per warp, 512 one-warp blocks.
// lane r (0..7) = j*2+p: j = hidden unit, p=0 -> gate rows (i_j, f_j),
// p=1 -> gate rows (g_j, o_j). Skewed wavefront: body(s) runs layer l at
// timestep s-l. All exchanges are xor-shuffles within the 8-lane group.
// Activation scales folded into weights; h-gather permutation folded into
// weight column order (W[row][j^m]).

#define TT 4096
#define BB 2048
#define LL 4

#define SGM (-1.4426950408889634f)   // -log2(e)
#define TGS (-2.8853900817779268f)   // -2*log2(e)

__device__ __forceinline__ float ex2f(float x) {
    float y; asm("ex2.approx.f32 %0, %1;" : "=f"(y) : "f"(x)); return y;
}
__device__ __forceinline__ float rcpf(float x) {
    float y; asm("rcp.approx.f32 %0, %1;" : "=f"(y) : "f"(x)); return y;
}

__global__ __launch_bounds__(32) void lstm_kernel(
    const float* __restrict__ x,     // (T, B, 2)
    const float* __restrict__ h0g,   // (L, B, 4)
    const float* __restrict__ c0g,   // (L, B, 4)
    const float* __restrict__ Wih0,  // (16, 2)
    const float* __restrict__ Wr,    // (3, 16, 4)  W_ih layers 1..3
    const float* __restrict__ Whh,   // (4, 16, 4)
    const float* __restrict__ bih,   // (4, 16)
    const float* __restrict__ bhh,   // (4, 16)
    float* __restrict__ out)         // ys (T,B,4) ++ hT (L,B,4) ++ cT (L,B,4)
{
    const int lane  = threadIdx.x & 31;
    const int q     = lane >> 3;              // batch sub-index 0..3
    const int r     = lane & 7;
    const int p     = r & 1;                  // 0: (i,f)  1: (g,o)
    const int j     = r >> 1;                 // hidden unit 0..3
    const int batch = blockIdx.x * 4 + q;

    // gate rows in the 16-row stacked gate matrix
    const int row0 = p ? (8 + j)  : j;        // g_j  or i_j
    const int row1 = p ? (12 + j) : (4 + j);  // o_j  or f_j
    const float s0 = p ? TGS : SGM;           // row0 activation scale
    const float s1 = SGM;                     // row1 always sigmoid

    // ---- weights (scales + h-gather permutation folded in) ----
    float wx0[2], wx1[2];                     // layer-0 input weights
    wx0[0] = Wih0[row0 * 2 + 0] * s0; wx0[1] = Wih0[row0 * 2 + 1] * s0;
    wx1[0] = Wih0[row1 * 2 + 0] * s1; wx1[1] = Wih0[row1 * 2 + 1] * s1;

    float wi0[3][4], wi1[3][4];               // layers 1..3 input weights
#pragma unroll
    for (int l = 0; l < 3; l++)
#pragma unroll
        for (int m = 0; m < 4; m++) {
            wi0[l][m] = Wr[(l * 16 + row0) * 4 + (j ^ m)] * s0;
            wi1[l][m] = Wr[(l * 16 + row1) * 4 + (j ^ m)] * s1;
        }

    float wh0[4][4], wh1[4][4], b0[4], b1[4];
#pragma unroll
    for (int l = 0; l < 4; l++) {
#pragma unroll
        for (int m = 0; m < 4; m++) {
            wh0[l][m] = Whh[(l * 16 + row0) * 4 + (j ^ m)] * s0;
            wh1[l][m] = Whh[(l * 16 + row1) * 4 + (j ^ m)] * s1;
        }
        b0[l] = (bih[l * 16 + row0] + bhh[l * 16 + row0]) * s0;
        b1[l] = (bih[l * 16 + row1] + bhh[l * 16 + row1]) * s1;
    }

    // ---- states ----
    float harr[4][4];   // harr[l][m] = h^{(l)}_{j^m}
    float c[4];         // c^{(l)}_j (replicated across the p pair)
#pragma unroll
    for (int l = 0; l < 4; l++) {
#pragma unroll
        for (int m = 0; m < 4; m++)
            harr[l][m] = h0g[(l * BB + batch) * 4 + (j ^ m)];
        c[l] = c0g[(l * BB + batch) * 4 + j];
    }

    float* __restrict__ ys  = out;
    float* __restrict__ hso = out + (size_t)TT * BB * 4;
    float* __restrict__ cso = hso + (size_t)LL * BB * 4;

    // running output pointer for layer-3 rows (strength-reduced)
    float4* __restrict__ ysp =
        reinterpret_cast<float4*>(ys) - 3 * BB + batch;

    const float* xb = x + batch * 2;
    float2 xa = *reinterpret_cast<const float2*>(xb);                  // x[0]
    float2 xn = *reinterpret_cast<const float2*>(xb + (size_t)BB * 2); // x[1]

    auto body = [&](int s, bool masked) {
        // prefetch x two bodies ahead
        int tp = s + 2; if (tp > TT - 1) tp = TT - 1;
        float2 xf = *reinterpret_cast<const float2*>(xb + (size_t)tp * BB * 2);

        // ---- pre-activations for all 4 layers (from old state) ----
        float z0[4], z1[4];
        {   // layer 0: input = x[s]
            float a = fmaf(wx0[0], xa.x, fmaf(wx0[1], xa.y, b0[0]));
            float b = fmaf(wx1[0], xa.x, fmaf(wx1[1], xa.y, b1[0]));
#pragma unroll
            for (int m = 0; m < 4; m++) {
                a = fmaf(wh0[0][m], harr[0][m], a);
                b = fmaf(wh1[0][m], harr[0][m], b);
            }
            z0[0] = a; z1[0] = b;
        }
#pragma unroll
        for (int l = 1; l < 4; l++) {
            float a = b0[l], b = b1[l];
#pragma unroll
            for (int m = 0; m < 4; m++) {
                a = fmaf(wi0[l - 1][m], harr[l - 1][m], a);
                b = fmaf(wi1[l - 1][m], harr[l - 1][m], b);
            }
#pragma unroll
            for (int m = 0; m < 4; m++) {
                a = fmaf(wh0[l][m], harr[l][m], a);
                b = fmaf(wh1[l][m], harr[l][m], b);
            }
            z0[l] = a; z1[l] = b;
        }

        // ---- four independent layer updates ----
#pragma unroll
        for (int l = 3; l >= 0; l--) {
            bool act = masked ? ((unsigned)(s - l) < (unsigned)TT) : true;

            float a0 = rcpf(1.0f + ex2f(z0[l]));   // p0: sigma(i)  p1: pre-tanh(g)
            float a1 = rcpf(1.0f + ex2f(z1[l]));   // p0: sigma(f)  p1: sigma(o)
            if (p) a0 = fmaf(a0, 2.0f, -1.0f);     // tanh(g)

            // pair exchange: p0 sends (sigma_f*c, sigma_i); p1 sends (tanh_g, sigma_o)
            float sendA = p ? a0 : a1 * c[l];
            float sendB = p ? a1 : a0;
            float recvA = __shfl_xor_sync(0xffffffffu, sendA, 1);
            float recvB = __shfl_xor_sync(0xffffffffu, sendB, 1);

            float cnew = fmaf(p ? recvB : sendB,    // sigma_i
                              p ? sendA : recvA,    // tanh_g
                              p ? recvA : sendA);   // sigma_f * c
            float so   = p ? sendB : recvB;         // sigma_o

            float t  = rcpf(1.0f + ex2f(cnew * TGS));
            float th = fmaf(t, 2.0f, -1.0f);        // tanh(cnew)
            float h  = so * th;

            // h all-gather across units (xor 2,4,6), order = j^m
            float g1 = __shfl_xor_sync(0xffffffffu, h, 2);
            float g2 = __shfl_xor_sync(0xffffffffu, h, 4);
            float g3 = __shfl_xor_sync(0xffffffffu, h, 6);

            if (act) {
                c[l] = cnew;
                harr[l][0] = h;  harr[l][1] = g1;
                harr[l][2] = g2; harr[l][3] = g3;
                if (l == 3 && r == 0) {
                    *ysp = make_float4(harr[3][0], harr[3][1],
                                       harr[3][2], harr[3][3]);
                }
            }
        }

        ysp += BB;
        xa = xn; xn = xf;
    };

    body(0, true); body(1, true); body(2, true);
#pragma unroll 1
    for (int s = 3; s < TT; s++) body(s, false);
    body(TT, true); body(TT + 1, true); body(TT + 2, true);

    // ---- final hT / cT ----
    if (r == 0) {   // j==0 lane: harr[l][m] = h_m in natural order
#pragma unroll
        for (int l = 0; l < 4; l++)
            *reinterpret_cast<float4*>(hso + (l * BB + batch) * 4) =
                make_float4(harr[l][0], harr[l][1], harr[l][2], harr[l][3]);
    }
    if (p == 0) {   // one lane per unit j
#pragma unroll
        for (int l = 0; l < 4; l++)
            cso[(l * BB + batch) * 4 + j] = c[l];
    }
}

extern "C" void kernel_launch(void* const* d_in, const int* in_sizes, int n_in,
                              void* d_out, int out_size) {
    (void)in_sizes; (void)n_in; (void)out_size;
    const float* x    = (const float*)d_in[0];
    const float* h0   = (const float*)d_in[1];
    const float* c0   = (const float*)d_in[2];
    const float* Wih0 = (const float*)d_in[3];
    const float* Wr   = (const float*)d_in[4];
    const float* Whh  = (const float*)d_in[5];
    const float* bih  = (const float*)d_in[6];
    const float* bhh  = (const float*)d_in[7];
    // 4 batch elements per warp, 1 warp per block: 512 blocks
    lstm_kernel<<<BB / 4, 32>>>(x, h0, c0, Wih0, Wr, Whh, bih, bhh, (float*)d_out);
}